// round 1
// baseline (speedup 1.0000x reference)
#include <cuda_runtime.h>
#include <math.h>

#define NN 100000
#define NE 1600000
#define D  128
#define NG 512
#define NC 10
#define SCAN_B 1024
#define N_SCAN_BLKS ((NN + SCAN_B - 1) / SCAN_B)   // 98

// ---------------- scratch (static device allocations; no cudaMalloc) --------
__device__ float g_buf[NN * D];          // g = dinv * (X @ W)
__device__ float h_buf[NN * D];          // layer output (post-relu)
__device__ int   d_deg[NN];
__device__ float d_dinv[NN];
__device__ int   d_offs[NN + 1];
__device__ int   d_cursor[NN];
__device__ int   d_csr[NE];
__device__ int   d_blksum[N_SCAN_BLKS];
__device__ float d_pooled[NG * D];
__device__ int   d_gstart[NG];
__device__ int   d_gend[NG];

// ---------------- helpers ---------------------------------------------------
__device__ __forceinline__ void add4(float4& a, const float4 b) {
    a.x += b.x; a.y += b.y; a.z += b.z; a.w += b.w;
}

// ---------------- CSR build -------------------------------------------------
__global__ void k_init() {
    int i = blockIdx.x * blockDim.x + threadIdx.x;
    if (i < NN) { d_deg[i] = 0; d_cursor[i] = 0; }
    if (i < NG) { d_gstart[i] = 0; d_gend[i] = 0; }
}

__global__ void k_hist(const int* __restrict__ dst) {
    int e = blockIdx.x * blockDim.x + threadIdx.x;
    if (e < NE) atomicAdd(&d_deg[dst[e]], 1);
}

__global__ void k_scan1() {
    __shared__ int s[SCAN_B];
    int t = threadIdx.x;
    int i = blockIdx.x * SCAN_B + t;
    int v = (i < NN) ? d_deg[i] : 0;
    s[t] = v;
    __syncthreads();
    for (int d = 1; d < SCAN_B; d <<= 1) {
        int x = (t >= d) ? s[t - d] : 0;
        __syncthreads();
        s[t] += x;
        __syncthreads();
    }
    if (i < NN) d_offs[i + 1] = s[t];
    if (t == SCAN_B - 1) d_blksum[blockIdx.x] = s[t];
}

__global__ void k_scan2() {   // single block of 128; N_SCAN_BLKS=98 <= 128
    __shared__ int s[128];
    int t = threadIdx.x;
    int v = (t < N_SCAN_BLKS) ? d_blksum[t] : 0;
    s[t] = v;
    __syncthreads();
    for (int d = 1; d < 128; d <<= 1) {
        int x = (t >= d) ? s[t - d] : 0;
        __syncthreads();
        s[t] += x;
        __syncthreads();
    }
    if (t < N_SCAN_BLKS) d_blksum[t] = s[t] - v;   // exclusive
}

__global__ void k_finalize() {
    int i = blockIdx.x * blockDim.x + threadIdx.x;
    if (i < NN) {
        d_offs[i + 1] += d_blksum[i >> 10];
        d_dinv[i] = rsqrtf((float)d_deg[i] + 1.0f);
        if (i == 0) d_offs[0] = 0;
    }
}

__global__ void k_place(const int* __restrict__ src, const int* __restrict__ dst) {
    int e = blockIdx.x * blockDim.x + threadIdx.x;
    if (e < NE) {
        int d = dst[e];
        int pos = d_offs[d] + atomicAdd(&d_cursor[d], 1);
        d_csr[pos] = src[e];
    }
}

// ---------------- GEMM: G = dinv * (X @ W), M=NN, N=K=128 -------------------
// 128x128 output tile, 256 threads, 8x8 microtile split as 4+4 rows/cols.
__global__ __launch_bounds__(256) void k_gemm(const float* __restrict__ X,
                                              const float* __restrict__ W,
                                              float* __restrict__ G) {
    __shared__ float As[32][D];   // k-major (transposed) A tile
    __shared__ float Bs[32][D];
    int tid = threadIdx.x;
    int m0  = blockIdx.x * 128;
    int tx  = tid & 15;
    int ty  = tid >> 4;

    float acc[8][8];
#pragma unroll
    for (int i = 0; i < 8; i++)
#pragma unroll
        for (int j = 0; j < 8; j++) acc[i][j] = 0.f;

    for (int k0 = 0; k0 < D; k0 += 32) {
        // load A tile (transpose into smem)
        {
            int row = tid >> 3;      // 0..31
            int fc  = tid & 7;       // float4 col 0..7
#pragma unroll
            for (int it = 0; it < 4; it++) {
                int r  = row + 32 * it;
                int gr = m0 + r;
                float4 v = make_float4(0.f, 0.f, 0.f, 0.f);
                if (gr < NN)
                    v = *(const float4*)&X[gr * D + k0 + fc * 4];
                As[fc * 4 + 0][r] = v.x;
                As[fc * 4 + 1][r] = v.y;
                As[fc * 4 + 2][r] = v.z;
                As[fc * 4 + 3][r] = v.w;
            }
        }
        // load B tile
        {
            int kr = tid >> 5;       // 0..7
            int nc = tid & 31;       // float4 col 0..31
#pragma unroll
            for (int it = 0; it < 4; it++) {
                int k = kr + 8 * it;
                *(float4*)&Bs[k][nc * 4] = *(const float4*)&W[(k0 + k) * D + nc * 4];
            }
        }
        __syncthreads();
#pragma unroll
        for (int kk = 0; kk < 32; kk++) {
            float a[8], b[8];
            *(float4*)(a)     = *(const float4*)&As[kk][ty * 4];
            *(float4*)(a + 4) = *(const float4*)&As[kk][64 + ty * 4];
            *(float4*)(b)     = *(const float4*)&Bs[kk][tx * 4];
            *(float4*)(b + 4) = *(const float4*)&Bs[kk][64 + tx * 4];
#pragma unroll
            for (int i = 0; i < 8; i++)
#pragma unroll
                for (int j = 0; j < 8; j++)
                    acc[i][j] = fmaf(a[i], b[j], acc[i][j]);
        }
        __syncthreads();
    }
    // epilogue: scale row by dinv
#pragma unroll
    for (int half = 0; half < 2; half++) {
#pragma unroll
        for (int i = 0; i < 4; i++) {
            int r  = half * 64 + ty * 4 + i;
            int gr = m0 + r;
            if (gr < NN) {
                float s  = d_dinv[gr];
                int   ai = half * 4 + i;
                float4 lo = make_float4(acc[ai][0] * s, acc[ai][1] * s,
                                        acc[ai][2] * s, acc[ai][3] * s);
                float4 hi = make_float4(acc[ai][4] * s, acc[ai][5] * s,
                                        acc[ai][6] * s, acc[ai][7] * s);
                *(float4*)&G[gr * D + tx * 4]      = lo;
                *(float4*)&G[gr * D + 64 + tx * 4] = hi;
            }
        }
    }
}

// ---------------- aggregation: out[i]=relu(dinv[i]*(g[i]+sum g[j]) + b) -----
__global__ __launch_bounds__(256) void k_agg(const float* __restrict__ g,
                                             const float* __restrict__ bias,
                                             float* __restrict__ out) {
    int node = (blockIdx.x * blockDim.x + threadIdx.x) >> 5;
    int lane = threadIdx.x & 31;
    if (node >= NN) return;
    const float4* g4 = (const float4*)g;

    float4 a0 = g4[node * 32 + lane];                    // self term g[i]
    float4 a1 = make_float4(0.f, 0.f, 0.f, 0.f);
    float4 a2 = a1, a3 = a1;

    int p = d_offs[node];
    int e = d_offs[node + 1];
    for (; p + 4 <= e; p += 4) {
        int j0 = d_csr[p], j1 = d_csr[p + 1], j2 = d_csr[p + 2], j3 = d_csr[p + 3];
        float4 v0 = g4[j0 * 32 + lane];
        float4 v1 = g4[j1 * 32 + lane];
        float4 v2 = g4[j2 * 32 + lane];
        float4 v3 = g4[j3 * 32 + lane];
        add4(a0, v0); add4(a1, v1); add4(a2, v2); add4(a3, v3);
    }
    for (; p < e; p++) add4(a0, g4[d_csr[p] * 32 + lane]);

    add4(a0, a1); add4(a2, a3); add4(a0, a2);
    float  sc = d_dinv[node];
    float4 b4 = ((const float4*)bias)[lane];
    float4 o;
    o.x = fmaxf(fmaf(sc, a0.x, b4.x), 0.f);
    o.y = fmaxf(fmaf(sc, a0.y, b4.y), 0.f);
    o.z = fmaxf(fmaf(sc, a0.z, b4.z), 0.f);
    o.w = fmaxf(fmaf(sc, a0.w, b4.w), 0.f);
    ((float4*)out)[node * 32 + lane] = o;
}

// ---------------- pooling + classifier --------------------------------------
__global__ void k_bounds(const int* __restrict__ batch) {
    int i = blockIdx.x * blockDim.x + threadIdx.x;
    if (i < NN) {
        int b = batch[i];
        if (i == 0 || batch[i - 1] != b) d_gstart[b] = i;
        if (i == NN - 1 || batch[i + 1] != b) d_gend[b] = i + 1;
    }
}

__global__ void k_pool(const float* __restrict__ h) {
    int g = blockIdx.x;
    int t = threadIdx.x;   // 128
    int s = d_gstart[g], e = d_gend[g];
    float sum = 0.f;
    for (int r = s; r < e; r++) sum += h[r * D + t];
    int cnt = e - s;
    d_pooled[g * D + t] = (cnt > 0) ? sum / (float)cnt : 0.f;
}

__global__ void k_cls(const float* __restrict__ Wc, const float* __restrict__ bc,
                      float* __restrict__ out) {
    int g = blockIdx.x;
    int t = threadIdx.x;   // 32
    if (t < NC) {
        float acc = bc[t];
#pragma unroll 8
        for (int k = 0; k < D; k++)
            acc = fmaf(d_pooled[g * D + k], Wc[k * NC + t], acc);
        out[g * NC + t] = acc;
    }
}

// ---------------- launch -----------------------------------------------------
extern "C" void kernel_launch(void* const* d_in, const int* in_sizes, int n_in,
                              void* d_out, int out_size) {
    const float* x     = (const float*)d_in[0];
    const int*   esrc  = (const int*)d_in[1];
    const int*   edst  = (const int*)d_in[2];
    const int*   batch = (const int*)d_in[3];
    const float* Ws[3] = {(const float*)d_in[4], (const float*)d_in[6], (const float*)d_in[8]};
    const float* bs[3] = {(const float*)d_in[5], (const float*)d_in[7], (const float*)d_in[9]};
    const float* Wc = (const float*)d_in[10];
    const float* bc = (const float*)d_in[11];
    float* out = (float*)d_out;

    float *pg = nullptr, *ph = nullptr;
    cudaGetSymbolAddress((void**)&pg, g_buf);
    cudaGetSymbolAddress((void**)&ph, h_buf);

    int nbN = (NN + 255) / 256;
    int nbE = (NE + 255) / 256;

    k_init<<<nbN, 256>>>();
    k_hist<<<nbE, 256>>>(edst);
    k_scan1<<<N_SCAN_BLKS, SCAN_B>>>();
    k_scan2<<<1, 128>>>();
    k_finalize<<<nbN, 256>>>();
    k_place<<<nbE, 256>>>(esrc, edst);

    const float* in = x;
    for (int l = 0; l < 3; l++) {
        k_gemm<<<(NN + 127) / 128, 256>>>(in, Ws[l], pg);
        k_agg<<<(NN * 32 + 255) / 256, 256>>>(pg, bs[l], ph);
        in = ph;
    }

    k_bounds<<<nbN, 256>>>(batch);
    k_pool<<<NG, D>>>(ph);
    k_cls<<<NG, 32>>>(Wc, bc, out);
}

// round 3
// speedup vs baseline: 1.1693x; 1.1693x over previous
#include <cuda_runtime.h>
#include <cuda_bf16.h>
#include <math.h>
#include <stdint.h>

#define NN 100000
#define NE 1600000
#define D  128
#define NG 512
#define NC 10
#define SCAN_B 1024
#define N_SCAN_BLKS ((NN + SCAN_B - 1) / SCAN_B)   // 98
#define GEMM_TILES ((NN + 127) / 128)              // 782
#define PADB 272                                   // smem row stride bytes (128 bf16 + 8 pad)
#define TILE_BYTES (128 * PADB)                    // 34816

// ---------------- scratch (static device allocations; no cudaMalloc) --------
__device__ float g_buf[NN * D];            // g = dinv * (A @ W)  (fp32)
__device__ float h_buf[NN * D];            // final layer output (post-relu)
__device__ __nv_bfloat16 ahi_buf[NN * D];  // split-hi of layer input
__device__ __nv_bfloat16 alo_buf[NN * D];  // split-lo of layer input
__device__ __nv_bfloat16 whi_buf[D * D];   // W^T split hi  [N=out, K=in]
__device__ __nv_bfloat16 wlo_buf[D * D];
__device__ int   d_deg[NN];
__device__ float d_dinv[NN];
__device__ int   d_offs[NN + 1];
__device__ int   d_cursor[NN];
__device__ int   d_csr[NE];
__device__ int   d_blksum[N_SCAN_BLKS];
__device__ float d_pooled[NG * D];
__device__ int   d_gstart[NG];
__device__ int   d_gend[NG];

// ---------------- PTX helpers (all sm_80-era, safe for compute_100) ---------
__device__ __forceinline__ uint32_t smem_u32(const void* p) {
    uint32_t a;
    asm("{ .reg .u64 t; cvta.to.shared.u64 t, %1; cvt.u32.u64 %0, t; }"
        : "=r"(a) : "l"(p));
    return a;
}
__device__ __forceinline__ void ldm_x4(uint32_t* r, uint32_t addr) {
    asm volatile("ldmatrix.sync.aligned.m8n8.x4.shared.b16 {%0,%1,%2,%3}, [%4];"
                 : "=r"(r[0]), "=r"(r[1]), "=r"(r[2]), "=r"(r[3]) : "r"(addr));
}
__device__ __forceinline__ void ldm_x2(uint32_t* r, uint32_t addr) {
    asm volatile("ldmatrix.sync.aligned.m8n8.x2.shared.b16 {%0,%1}, [%2];"
                 : "=r"(r[0]), "=r"(r[1]) : "r"(addr));
}
__device__ __forceinline__ void mma16816(float* c, const uint32_t* a,
                                         const uint32_t* b) {
    asm volatile(
        "mma.sync.aligned.m16n8k16.row.col.f32.bf16.bf16.f32 "
        "{%0,%1,%2,%3}, {%4,%5,%6,%7}, {%8,%9}, {%0,%1,%2,%3};"
        : "+f"(c[0]), "+f"(c[1]), "+f"(c[2]), "+f"(c[3])
        : "r"(a[0]), "r"(a[1]), "r"(a[2]), "r"(a[3]), "r"(b[0]), "r"(b[1]));
}
#define STS128U(addr, v)                                                     \
    asm volatile("st.shared.v4.b32 [%0], {%1, %2, %3, %4};" ::"r"(addr),     \
                 "r"(v.x), "r"(v.y), "r"(v.z), "r"(v.w) : "memory")

// ---------------- CSR build -------------------------------------------------
__global__ void k_init() {
    int i = blockIdx.x * blockDim.x + threadIdx.x;
    if (i < NN) { d_deg[i] = 0; d_cursor[i] = 0; }
    if (i < NG) { d_gstart[i] = 0; d_gend[i] = 0; }
}
__global__ void k_hist(const int* __restrict__ dst) {
    int e = blockIdx.x * blockDim.x + threadIdx.x;
    if (e < NE) atomicAdd(&d_deg[dst[e]], 1);
}
__global__ void k_scan1() {
    __shared__ int s[SCAN_B];
    int t = threadIdx.x;
    int i = blockIdx.x * SCAN_B + t;
    int v = (i < NN) ? d_deg[i] : 0;
    s[t] = v;
    __syncthreads();
    for (int d = 1; d < SCAN_B; d <<= 1) {
        int x = (t >= d) ? s[t - d] : 0;
        __syncthreads();
        s[t] += x;
        __syncthreads();
    }
    if (i < NN) d_offs[i + 1] = s[t];
    if (t == SCAN_B - 1) d_blksum[blockIdx.x] = s[t];
}
__global__ void k_scan2() {
    __shared__ int s[128];
    int t = threadIdx.x;
    int v = (t < N_SCAN_BLKS) ? d_blksum[t] : 0;
    s[t] = v;
    __syncthreads();
    for (int d = 1; d < 128; d <<= 1) {
        int x = (t >= d) ? s[t - d] : 0;
        __syncthreads();
        s[t] += x;
        __syncthreads();
    }
    if (t < N_SCAN_BLKS) d_blksum[t] = s[t] - v;
}
__global__ void k_finalize() {
    int i = blockIdx.x * blockDim.x + threadIdx.x;
    if (i < NN) {
        d_offs[i + 1] += d_blksum[i >> 10];
        d_dinv[i] = rsqrtf((float)d_deg[i] + 1.0f);
        if (i == 0) d_offs[0] = 0;
    }
}
__global__ void k_place(const int* __restrict__ src, const int* __restrict__ dst) {
    int e = blockIdx.x * blockDim.x + threadIdx.x;
    if (e < NE) {
        int d = dst[e];
        int pos = d_offs[d] + atomicAdd(&d_cursor[d], 1);
        d_csr[pos] = src[e];
    }
}

// ---------------- input / weight splitting ----------------------------------
__global__ void k_splitX(const float* __restrict__ X) {
    int i = blockIdx.x * blockDim.x + threadIdx.x;   // one float4
    if (i < NN * (D / 4)) {
        float4 v = ((const float4*)X)[i];
        __nv_bfloat16 h0 = __float2bfloat16(v.x), h1 = __float2bfloat16(v.y);
        __nv_bfloat16 h2 = __float2bfloat16(v.z), h3 = __float2bfloat16(v.w);
        __nv_bfloat16 l0 = __float2bfloat16(v.x - __bfloat162float(h0));
        __nv_bfloat16 l1 = __float2bfloat16(v.y - __bfloat162float(h1));
        __nv_bfloat16 l2 = __float2bfloat16(v.z - __bfloat162float(h2));
        __nv_bfloat16 l3 = __float2bfloat16(v.w - __bfloat162float(h3));
        __nv_bfloat162* hp = (__nv_bfloat162*)ahi_buf;
        __nv_bfloat162* lp = (__nv_bfloat162*)alo_buf;
        hp[i * 2]     = __nv_bfloat162(h0, h1);
        hp[i * 2 + 1] = __nv_bfloat162(h2, h3);
        lp[i * 2]     = __nv_bfloat162(l0, l1);
        lp[i * 2 + 1] = __nv_bfloat162(l2, l3);
    }
}
// W [K=in,N=out] fp32 -> B [N,K] bf16 hi/lo (transposed: col-major B for mma)
__global__ void k_prepW(const float* __restrict__ W) {
    int idx = blockIdx.x * blockDim.x + threadIdx.x;   // n*128 + k
    if (idx < D * D) {
        int n = idx >> 7, k = idx & 127;
        float v = W[k * D + n];
        __nv_bfloat16 h = __float2bfloat16(v);
        whi_buf[idx] = h;
        wlo_buf[idx] = __float2bfloat16(v - __bfloat162float(h));
    }
}

// ---------------- tensor-core GEMM: G = dinv * (A @ W) ----------------------
// 256 threads, 128x128 CTA tile, warp tile 64x32, mma.sync m16n8k16 bf16,
// 3-term hi/lo split accumulated into shared fp32 accumulators.
__global__ __launch_bounds__(256) void k_gemm_mma(float* __restrict__ G) {
    extern __shared__ char sm[];
    uint32_t sb = smem_u32(sm);
    uint32_t AH = sb, AL = sb + TILE_BYTES, BH = sb + 2 * TILE_BYTES,
             BL = sb + 3 * TILE_BYTES;
    int tid = threadIdx.x, wid = tid >> 5, lid = tid & 31;
    int wm = wid >> 2, wn = wid & 3;
    int m0 = blockIdx.x * 128;

    // ---- load tiles to smem (padded rows, 16B chunks) ----
    const uint4* Ah4 = (const uint4*)ahi_buf;
    const uint4* Al4 = (const uint4*)alo_buf;
    const uint4* Bh4 = (const uint4*)whi_buf;
    const uint4* Bl4 = (const uint4*)wlo_buf;
#pragma unroll
    for (int q = tid; q < 2048; q += 256) {
        int r = q >> 4, j = q & 15;
        uint32_t off = (uint32_t)(r * PADB + j * 16);
        int gr = m0 + r;
        uint4 vh = make_uint4(0, 0, 0, 0), vl = vh;
        if (gr < NN) { vh = Ah4[gr * 16 + j]; vl = Al4[gr * 16 + j]; }
        STS128U(AH + off, vh);
        STS128U(AL + off, vl);
        uint4 wh = Bh4[q], wl = Bl4[q];
        STS128U(BH + off, wh);
        STS128U(BL + off, wl);
    }
    __syncthreads();

    float c[4][4][4];
#pragma unroll
    for (int mi = 0; mi < 4; mi++)
#pragma unroll
        for (int ni = 0; ni < 4; ni++)
#pragma unroll
            for (int e = 0; e < 4; e++) c[mi][ni][e] = 0.f;

    // ldmatrix address bases
    int l16 = lid & 15;
    uint32_t aBase = (uint32_t)((wm * 64 + l16) * PADB + (((lid >> 4) << 3) << 1));
    uint32_t bBase = (uint32_t)((wn * 32 + (l16 & 7)) * PADB + (((l16 >> 3) << 3) << 1));

#pragma unroll
    for (int ks = 0; ks < 8; ks++) {
        int k0b = ks * 32;   // k0 * 2 bytes
        uint32_t ah[4][4], al[4][4], bh[4][2], bl[4][2];
#pragma unroll
        for (int mi = 0; mi < 4; mi++) {
            uint32_t ad = aBase + (uint32_t)(mi * 16 * PADB + k0b);
            ldm_x4(ah[mi], AH + ad);
            ldm_x4(al[mi], AL + ad);
        }
#pragma unroll
        for (int ni = 0; ni < 4; ni++) {
            uint32_t bd = bBase + (uint32_t)(ni * 8 * PADB + k0b);
            ldm_x2(bh[ni], BH + bd);
            ldm_x2(bl[ni], BL + bd);
        }
#pragma unroll
        for (int mi = 0; mi < 4; mi++)
#pragma unroll
            for (int ni = 0; ni < 4; ni++) {
                mma16816(c[mi][ni], ah[mi], bh[ni]);
                mma16816(c[mi][ni], ah[mi], bl[ni]);
                mma16816(c[mi][ni], al[mi], bh[ni]);
            }
    }

    // ---- epilogue: scale rows by dinv, store fp32 ----
    int lq = lid >> 2, lr = lid & 3;
#pragma unroll
    for (int mi = 0; mi < 4; mi++) {
        int r0 = m0 + wm * 64 + mi * 16 + lq;
        int r1 = r0 + 8;
        float s0 = (r0 < NN) ? d_dinv[r0] : 0.f;
        float s1 = (r1 < NN) ? d_dinv[r1] : 0.f;
#pragma unroll
        for (int ni = 0; ni < 4; ni++) {
            int col = wn * 32 + ni * 8 + lr * 2;
            if (r0 < NN) {
                float2 o = make_float2(c[mi][ni][0] * s0, c[mi][ni][1] * s0);
                *(float2*)&G[r0 * D + col] = o;
            }
            if (r1 < NN) {
                float2 o = make_float2(c[mi][ni][2] * s1, c[mi][ni][3] * s1);
                *(float2*)&G[r1 * D + col] = o;
            }
        }
    }
}

// ---------------- aggregation -----------------------------------------------
__device__ __forceinline__ void add4(float4& a, const float4 b) {
    a.x += b.x; a.y += b.y; a.z += b.z; a.w += b.w;
}
// o = relu(dinv[i]*(g[i]+sum g[j]) + b); MODE 0: emit bf16 hi/lo split for the
// next layer's GEMM; MODE 1: emit fp32 h_buf for pooling.
template <int MODE>
__global__ __launch_bounds__(256) void k_agg(const float* __restrict__ g,
                                             const float* __restrict__ bias) {
    int node = (blockIdx.x * blockDim.x + threadIdx.x) >> 5;
    int lane = threadIdx.x & 31;
    if (node >= NN) return;
    const float4* g4 = (const float4*)g;

    float4 a0 = g4[node * 32 + lane];   // self term
    float4 a1 = make_float4(0.f, 0.f, 0.f, 0.f);
    float4 a2 = a1, a3 = a1;

    int p = d_offs[node];
    int e = d_offs[node + 1];
    for (; p + 4 <= e; p += 4) {
        int j0 = d_csr[p], j1 = d_csr[p + 1], j2 = d_csr[p + 2], j3 = d_csr[p + 3];
        add4(a0, g4[j0 * 32 + lane]);
        add4(a1, g4[j1 * 32 + lane]);
        add4(a2, g4[j2 * 32 + lane]);
        add4(a3, g4[j3 * 32 + lane]);
    }
    for (; p < e; p++) add4(a0, g4[d_csr[p] * 32 + lane]);
    add4(a0, a1); add4(a2, a3); add4(a0, a2);

    float  sc = d_dinv[node];
    float4 b4 = ((const float4*)bias)[lane];
    float4 o;
    o.x = fmaxf(fmaf(sc, a0.x, b4.x), 0.f);
    o.y = fmaxf(fmaf(sc, a0.y, b4.y), 0.f);
    o.z = fmaxf(fmaf(sc, a0.z, b4.z), 0.f);
    o.w = fmaxf(fmaf(sc, a0.w, b4.w), 0.f);

    if (MODE == 1) {
        ((float4*)h_buf)[node * 32 + lane] = o;
    } else {
        __nv_bfloat16 h0 = __float2bfloat16(o.x), h1 = __float2bfloat16(o.y);
        __nv_bfloat16 h2 = __float2bfloat16(o.z), h3 = __float2bfloat16(o.w);
        __nv_bfloat16 l0 = __float2bfloat16(o.x - __bfloat162float(h0));
        __nv_bfloat16 l1 = __float2bfloat16(o.y - __bfloat162float(h1));
        __nv_bfloat16 l2 = __float2bfloat16(o.z - __bfloat162float(h2));
        __nv_bfloat16 l3 = __float2bfloat16(o.w - __bfloat162float(h3));
        __nv_bfloat162* hp = (__nv_bfloat162*)ahi_buf;
        __nv_bfloat162* lp = (__nv_bfloat162*)alo_buf;
        int i = node * 64 + lane * 2;
        hp[i]     = __nv_bfloat162(h0, h1);
        hp[i + 1] = __nv_bfloat162(h2, h3);
        lp[i]     = __nv_bfloat162(l0, l1);
        lp[i + 1] = __nv_bfloat162(l2, l3);
    }
}

// ---------------- pooling + classifier --------------------------------------
__global__ void k_bounds(const int* __restrict__ batch) {
    int i = blockIdx.x * blockDim.x + threadIdx.x;
    if (i < NN) {
        int b = batch[i];
        if (i == 0 || batch[i - 1] != b) d_gstart[b] = i;
        if (i == NN - 1 || batch[i + 1] != b) d_gend[b] = i + 1;
    }
}
__global__ void k_pool(const float* __restrict__ h) {
    int g = blockIdx.x;
    int t = threadIdx.x;
    int s = d_gstart[g], e = d_gend[g];
    float sum = 0.f;
    for (int r = s; r < e; r++) sum += h[r * D + t];
    int cnt = e - s;
    d_pooled[g * D + t] = (cnt > 0) ? sum / (float)cnt : 0.f;
}
__global__ void k_cls(const float* __restrict__ Wc, const float* __restrict__ bc,
                      float* __restrict__ out) {
    int g = blockIdx.x;
    int t = threadIdx.x;
    if (t < NC) {
        float acc = bc[t];
#pragma unroll 8
        for (int k = 0; k < D; k++)
            acc = fmaf(d_pooled[g * D + k], Wc[k * NC + t], acc);
        out[g * NC + t] = acc;
    }
}

// ---------------- launch -----------------------------------------------------
extern "C" void kernel_launch(void* const* d_in, const int* in_sizes, int n_in,
                              void* d_out, int out_size) {
    const float* x     = (const float*)d_in[0];
    const int*   esrc  = (const int*)d_in[1];
    const int*   edst  = (const int*)d_in[2];
    const int*   batch = (const int*)d_in[3];
    const float* Ws[3] = {(const float*)d_in[4], (const float*)d_in[6], (const float*)d_in[8]};
    const float* bs[3] = {(const float*)d_in[5], (const float*)d_in[7], (const float*)d_in[9]};
    const float* Wc = (const float*)d_in[10];
    const float* bc = (const float*)d_in[11];
    float* out = (float*)d_out;

    float *pg = nullptr, *ph = nullptr;
    cudaGetSymbolAddress((void**)&pg, g_buf);
    cudaGetSymbolAddress((void**)&ph, h_buf);

    const int SMEM_SZ = 4 * TILE_BYTES;   // 139264
    cudaFuncSetAttribute(k_gemm_mma, cudaFuncAttributeMaxDynamicSharedMemorySize,
                         SMEM_SZ);

    int nbN = (NN + 255) / 256;
    int nbE = (NE + 255) / 256;

    k_init<<<nbN, 256>>>();
    k_hist<<<nbE, 256>>>(edst);
    k_scan1<<<N_SCAN_BLKS, SCAN_B>>>();
    k_scan2<<<1, 128>>>();
    k_finalize<<<nbN, 256>>>();
    k_place<<<nbE, 256>>>(esrc, edst);

    k_splitX<<<(NN * 32 + 255) / 256, 256>>>(x);
    for (int l = 0; l < 3; l++) {
        k_prepW<<<(D * D + 255) / 256, 256>>>(Ws[l]);
        k_gemm_mma<<<GEMM_TILES, 256, SMEM_SZ>>>(pg);
        if (l < 2)
            k_agg<0><<<(NN * 32 + 255) / 256, 256>>>(pg, bs[l]);
        else
            k_agg<1><<<(NN * 32 + 255) / 256, 256>>>(pg, bs[l]);
    }

    k_bounds<<<nbN, 256>>>(batch);
    k_pool<<<NG, D>>>(ph);
    k_cls<<<NG, 32>>>(Wc, bc, out);
}